// round 16
// baseline (speedup 1.0000x reference)
#include <cuda_runtime.h>
#include <cuda_bf16.h>

#define BB 4
#define SS 2048
#define DD 1024
#define HH 16
#define HD 64

typedef unsigned long long u64;
typedef unsigned int u32;
typedef unsigned short u16;

// ---- cp.async ----
#define CP16(dst, src) \
    asm volatile("cp.async.cg.shared.global [%0], [%1], 16;" :: "r"(dst), "l"(src))
#define CPC asm volatile("cp.async.commit_group;")
#define CPW(n) asm volatile("cp.async.wait_group %0;" :: "n"(n))

// ---- bf16 helpers ----
__device__ __forceinline__ u32 pkbf2(float a, float b) {
    __nv_bfloat162 t = __floats2bfloat162_rn(a, b);
    return *reinterpret_cast<u32*>(&t);
}
__device__ __forceinline__ float bf2f(u16 h) {
    __nv_bfloat16 t = *reinterpret_cast<__nv_bfloat16*>(&h);
    return __bfloat162float(t);
}
__device__ __forceinline__ void split2(float a, float b, u32& hi, u32& lo) {
    hi = pkbf2(a, b);
    float ra = a - bf2f((u16)(hi & 0xffff));
    float rb = b - bf2f((u16)(hi >> 16));
    lo = pkbf2(ra, rb);
}
__device__ __forceinline__ u32 smem_u32(const void* p) {
    u32 a;
    asm("{ .reg .u64 t; cvta.to.shared.u64 t, %1; cvt.u32.u64 %0, t; }"
        : "=r"(a) : "l"(p));
    return a;
}

// mma.sync m16n8k16 bf16
__device__ __forceinline__ void mma16816(float* d, const u32* a, const u32* b) {
    asm volatile(
        "mma.sync.aligned.m16n8k16.row.col.f32.bf16.bf16.f32 "
        "{%0,%1,%2,%3}, {%4,%5,%6,%7}, {%8,%9}, {%0,%1,%2,%3};"
        : "+f"(d[0]), "+f"(d[1]), "+f"(d[2]), "+f"(d[3])
        : "r"(a[0]), "r"(a[1]), "r"(a[2]), "r"(a[3]), "r"(b[0]), "r"(b[1]));
}

// kpair permutation within each k16 group: [0,4,1,5,2,6,3,7]
__device__ __forceinline__ int kperm(int g) {
    int j = g & 7;
    return (g & ~7) | (2 * (j & 3) + (j >> 2));
}

// ---- device scratch (R10-proven layouts) ----
__device__ uint2 d_Xi[8192 * 512];
__device__ uint2 d_Wqi[3072 * 512];
__device__ uint2 d_Woi[1024 * 512];
__device__ uint2 d_Qi[(size_t)BB * HH * SS * 32];
__device__ uint2 d_Ki[(size_t)BB * HH * SS * 32];
__device__ u16   d_Vth[(size_t)BB * HH * HD * SS];
__device__ u16   d_Vtl[(size_t)BB * HH * HD * SS];
__device__ uint2 d_Ci[8192 * 512];
__device__ int   d_mask_nz;

// ---------------------------------------------------------------------------
// mask zero-check
// ---------------------------------------------------------------------------
__global__ void mask_zero_flag() {
    if (blockIdx.x == 0 && threadIdx.x == 0) d_mask_nz = 0;
}
__global__ void mask_check(const float* __restrict__ mask) {
    const int N = SS * SS / 4;
    int nz = 0;
    for (int i = blockIdx.x * blockDim.x + threadIdx.x; i < N;
         i += gridDim.x * blockDim.x) {
        float4 v = ((const float4*)mask)[i];
        if (v.x != 0.f || v.y != 0.f || v.z != 0.f || v.w != 0.f) nz = 1;
    }
    if (__syncthreads_or(nz) && threadIdx.x == 0) d_mask_nz = 1;
}

// ---------------------------------------------------------------------------
// prep: fp32 -> interleaved {hi,lo}, kpair-permuted
// ---------------------------------------------------------------------------
__global__ void prep_x(const float* __restrict__ X) {
    const int N = 8192 * 256;  // float4 count
    for (int i = blockIdx.x * blockDim.x + threadIdx.x; i < N;
         i += gridDim.x * blockDim.x) {
        float4 v = ((const float4*)X)[i];
        u32 h0, l0, h1, l1;
        split2(v.x, v.y, h0, l0);
        split2(v.z, v.w, h1, l1);
        int row = i >> 8, g2 = (i & 255) * 2;
        d_Xi[(size_t)row * 512 + kperm(g2)]     = make_uint2(h0, l0);
        d_Xi[(size_t)row * 512 + kperm(g2 + 1)] = make_uint2(h1, l1);
    }
}

template <int NTOT>
__global__ void prep_wt(const float* __restrict__ W, uint2* __restrict__ Wt) {
    __shared__ uint2 s[32][33];
    int tx = threadIdx.x, ty = threadIdx.y;
    int n  = blockIdx.x * 32 + tx;
    int k2 = blockIdx.y * 32 + ty;
    float w0 = W[(size_t)(2 * k2) * NTOT + n];
    float w1 = W[(size_t)(2 * k2 + 1) * NTOT + n];
    u32 h, l;
    split2(w0, w1, h, l);
    s[ty][tx] = make_uint2(h, l);
    __syncthreads();
    int outn = blockIdx.x * 32 + ty;
    int outk = blockIdx.y * 32 + tx;
    Wt[(size_t)outn * 512 + kperm(outk)] = s[tx][ty];
}

// ---------------------------------------------------------------------------
// GEMM: 6-buffer cp.async pipeline, k16 chunks, sync every 2 chunks.
// Same per-chunk compute code as R10; lookahead preserved (1 group = 2 chunks).
// ---------------------------------------------------------------------------
#define MM_SMEM (6 * 16384)

template <int MODE>
__global__ void __launch_bounds__(256, 2) mm_bf16(const uint2* __restrict__ Ai,
                                                  const uint2* __restrict__ Bi,
                                                  const float* __restrict__ bias,
                                                  float* __restrict__ outp) {
    extern __shared__ uint4 dynsm4[];
    const u32 sb = smem_u32(dynsm4);

    const int tid  = threadIdx.x;
    const int wid  = tid >> 5, lane = tid & 31;
    const int wm   = wid & 1, wn = wid >> 1;
    const int m0   = blockIdx.y * 128;
    const int n0   = blockIdx.x * 128;
    const int lq   = lane >> 2;
    const int lr   = lane & 3;

    const int srow = tid >> 1;
    const int sp   = (tid & 1) * 2;
    const uint2* aS = Ai + (size_t)(m0 + srow) * 512 + sp * 2;
    const uint2* bS = Bi + (size_t)(n0 + srow) * 512 + sp * 2;
    const u32 dAb = sb + srow * 64 + sp * 16;
    const u32 dBb = sb + 8192 + srow * 64 + sp * 16;

    float d[4][4][4];
#pragma unroll
    for (int mt = 0; mt < 4; mt++)
#pragma unroll
        for (int nt = 0; nt < 4; nt++)
#pragma unroll
            for (int e = 0; e < 4; e++) d[mt][nt][e] = 0.f;

    // prologue: stage chunks 0..3 as two groups of two chunks
#pragma unroll
    for (int g = 0; g < 2; g++) {
#pragma unroll
        for (int u = 0; u < 2; u++) {
            const int c   = 2 * g + u;
            const u32 off = c * 16384;
            CP16(dAb + off, aS + c * 8);
            CP16(dAb + off + 16, aS + c * 8 + 2);
            CP16(dBb + off, bS + c * 8);
            CP16(dBb + off + 16, bS + c * 8 + 2);
        }
        CPC;
    }

    int bufc = 0;  // buffer index of chunk cc
    for (int cc = 0; cc < 64; cc += 2) {
        CPW(1);
        __syncthreads();

        // compute chunks cc and cc+1 (bufs bufc, bufc+1; bufc is even)
#pragma unroll
        for (int u = 0; u < 2; u++) {
            const uint4* A4 = dynsm4 + (bufc + u) * 1024;
            const uint4* B4 = A4 + 512;

            u32 bh[4][2], bl[4][2];
#pragma unroll
            for (int nt = 0; nt < 4; nt++) {
                uint4 v = B4[(wn * 32 + nt * 8 + lq) * 4 + lr];
                bh[nt][0] = v.x; bh[nt][1] = v.z;
                bl[nt][0] = v.y; bl[nt][1] = v.w;
            }
#pragma unroll
            for (int mt = 0; mt < 4; mt++) {
                int row  = wm * 64 + mt * 16 + lq;
                uint4 v0 = A4[row * 4 + lr];
                uint4 v1 = A4[(row + 8) * 4 + lr];
                u32 ah[4] = {v0.x, v1.x, v0.z, v1.z};
                u32 al[4] = {v0.y, v1.y, v0.w, v1.w};
#pragma unroll
                for (int nt = 0; nt < 4; nt++) {
                    mma16816(d[mt][nt], ah, bh[nt]);
                    mma16816(d[mt][nt], ah, bl[nt]);
                    mma16816(d[mt][nt], al, bh[nt]);
                }
            }
        }

        // stage chunks cc+4, cc+5 into bufs (bufc+4)%6, (bufc+5)%6
        if (cc + 4 < 64) {
            const int b4 = (bufc + 4) % 6;
            const int b5 = (bufc + 5) % 6;
            const u32 o4 = b4 * 16384, o5 = b5 * 16384;
            const int c4 = cc + 4, c5 = cc + 5;
            CP16(dAb + o4, aS + c4 * 8);
            CP16(dAb + o4 + 16, aS + c4 * 8 + 2);
            CP16(dBb + o4, bS + c4 * 8);
            CP16(dBb + o4 + 16, bS + c4 * 8 + 2);
            CP16(dAb + o5, aS + c5 * 8);
            CP16(dAb + o5 + 16, aS + c5 * 8 + 2);
            CP16(dBb + o5, bS + c5 * 8);
            CP16(dBb + o5 + 16, bS + c5 * 8 + 2);
        }
        CPC;  // empty group at tail keeps wait-count uniform

        bufc += 2;
        if (bufc >= 6) bufc -= 6;
    }

    // --- epilogue (R10) ---
#pragma unroll
    for (int mt = 0; mt < 4; mt++) {
#pragma unroll
        for (int nt = 0; nt < 4; nt++) {
            int m = m0 + wm * 64 + mt * 16 + lq;
            int n = n0 + wn * 32 + nt * 8 + lr * 2;
            float2 bv = *(const float2*)&bias[n];
            float o00 = d[mt][nt][0] + bv.x, o01 = d[mt][nt][1] + bv.y;
            float o10 = d[mt][nt][2] + bv.x, o11 = d[mt][nt][3] + bv.y;
            if (MODE == 1) {
                *(float2*)&outp[(size_t)m * 1024 + n]       = make_float2(o00, o01);
                *(float2*)&outp[(size_t)(m + 8) * 1024 + n] = make_float2(o10, o11);
            } else {
                int bb = m >> 11, ssq = m & 2047;
                int which = n >> 10;
                int head  = (n & 1023) >> 6;
                int hd    = n & 63;
                u32 h0, l0, h1, l1;
                split2(o00, o01, h0, l0);
                split2(o10, o11, h1, l1);
                if (which < 2) {
                    uint2* dst = (which == 0) ? d_Qi : d_Ki;
                    size_t idx =
                        (((size_t)bb * HH + head) * SS + ssq) * 32 + (hd >> 1);
                    dst[idx]       = make_uint2(h0, l0);
                    dst[idx + 256] = make_uint2(h1, l1);
                } else {
                    size_t base = (((size_t)bb * HH + head) * HD + hd) * SS;
                    d_Vth[base + ssq]          = (u16)(h0 & 0xffff);
                    d_Vth[base + SS + ssq]     = (u16)(h0 >> 16);
                    d_Vtl[base + ssq]          = (u16)(l0 & 0xffff);
                    d_Vtl[base + SS + ssq]     = (u16)(l0 >> 16);
                    d_Vth[base + ssq + 8]      = (u16)(h1 & 0xffff);
                    d_Vth[base + SS + ssq + 8] = (u16)(h1 >> 16);
                    d_Vtl[base + ssq + 8]      = (u16)(l1 & 0xffff);
                    d_Vtl[base + SS + ssq + 8] = (u16)(l1 >> 16);
                }
            }
        }
    }
}

// ---------------------------------------------------------------------------
// Flash attention — EXACT R15 winner (log2-domain softmax, mask-skip).
// ---------------------------------------------------------------------------
#define AT_SMEM (2 * 36864)

__global__ void __launch_bounds__(256, 2) attn_mma(const float* __restrict__ mask) {
    extern __shared__ char atsm[];
    const u32 sb = smem_u32(atsm);

    const int tid  = threadIdx.x;
    const int wid  = tid >> 5, lane = tid & 31;
    const int lq   = lane >> 2, lr = lane & 3;
    const int qt = blockIdx.x, h = blockIdx.y, b = blockIdx.z;
    const size_t bh = (size_t)b * HH + h;
    const int q0 = qt * 128;
    const int qw = q0 + wid * 16;
    const int mnz = d_mask_nz;   // uniform

    u32 qfh[4][4], qfl[4][4];
    {
        const uint2* qp  = d_Qi + (bh * SS + qw + lq) * 32;
        const uint2* qp1 = qp + 256;
#pragma unroll
        for (int kc = 0; kc < 4; kc++) {
            uint2 a0 = qp[8 * kc + lr];
            uint2 a1 = qp1[8 * kc + lr];
            uint2 a2 = qp[8 * kc + 4 + lr];
            uint2 a3 = qp1[8 * kc + 4 + lr];
            qfh[kc][0] = a0.x; qfh[kc][1] = a1.x; qfh[kc][2] = a2.x; qfh[kc][3] = a3.x;
            qfl[kc][0] = a0.y; qfl[kc][1] = a1.y; qfl[kc][2] = a2.y; qfl[kc][3] = a3.y;
        }
    }

    float o[8][4];
#pragma unroll
    for (int nt = 0; nt < 8; nt++)
#pragma unroll
        for (int e = 0; e < 4; e++) o[nt][e] = 0.f;
    float m0r = -1e30f, m1r = -1e30f, l0r = 0.f, l1r = 0.f;

    const float LOG2E  = 1.44269504f;
    const float scale2 = 0.125f * LOG2E;
    const float* mp0 = mask + (size_t)(qw + lq) * SS;
    const float* mp1 = mask + (size_t)(qw + lq + 8) * SS;

    const int krow = tid >> 2, ku = (tid & 3) * 4;
    const int vrow = tid >> 2, vu = (tid & 3) * 2;
    const uint2* kSrc = d_Ki + (bh * SS + krow) * 32 + ku * 2;
    const char* vhSrc = (const char*)d_Vth + ((bh * HD + vrow) * SS) * 2 + vu * 16;
    const char* vlSrc = (const char*)d_Vtl + ((bh * HD + vrow) * SS) * 2 + vu * 16;
    const u32 dK  = sb + krow * 288 + ku * 16;
    const u32 dVh = sb + 18432 + vrow * 144 + vu * 16;
    const u32 dVl = sb + 27648 + vrow * 144 + vu * 16;

#pragma unroll
    for (int q = 0; q < 4; q++) CP16(dK + q * 16, kSrc + q * 2);
#pragma unroll
    for (int q = 0; q < 2; q++) {
        CP16(dVh + q * 16, vhSrc + q * 16);
        CP16(dVl + q * 16, vlSrc + q * 16);
    }
    CPC;

    for (int kt = 0; kt < SS / 64; kt++) {
        const int k0  = kt * 64;
        const int buf = kt & 1;
        if (kt < 31) {
            const u32 off = ((kt + 1) & 1) * 36864;
            const uint2* kN = kSrc + (size_t)(kt + 1) * 64 * 32;
            const char* vhN = vhSrc + (kt + 1) * 128;
            const char* vlN = vlSrc + (kt + 1) * 128;
#pragma unroll
            for (int q = 0; q < 4; q++) CP16(dK + off + q * 16, kN + q * 2);
#pragma unroll
            for (int q = 0; q < 2; q++) {
                CP16(dVh + off + q * 16, vhN + q * 16);
                CP16(dVl + off + q * 16, vlN + q * 16);
            }
            CPC;
            CPW(1);
        } else {
            CPW(0);
        }
        __syncthreads();

        const uint2* K2 = (const uint2*)(atsm + buf * 36864);
        const u32* Vh   = (const u32*)(atsm + buf * 36864 + 18432);
        const u32* Vl   = (const u32*)(atsm + buf * 36864 + 27648);

        float s[8][4];
#pragma unroll
        for (int nt = 0; nt < 8; nt++)
#pragma unroll
            for (int e = 0; e < 4; e++) s[nt][e] = 0.f;

#pragma unroll
        for (int kc = 0; kc < 4; kc++) {
#pragma unroll
            for (int nt = 0; nt < 8; nt++) {
                int base = (nt * 8 + lq) * 36 + 8 * kc + lr;
                uint2 r0 = K2[base];
                uint2 r1 = K2[base + 4];
                u32 bhf[2] = {r0.x, r1.x};
                u32 blf[2] = {r0.y, r1.y};
                mma16816(s[nt], qfh[kc], bhf);
                mma16816(s[nt], qfh[kc], blf);
                mma16816(s[nt], qfl[kc], bhf);
            }
        }

        if (mnz) {
#pragma unroll
            for (int nt = 0; nt < 8; nt++) {
                float2 ma = *(const float2*)(mp0 + k0 + nt * 8 + 2 * lr);
                float2 mb = *(const float2*)(mp1 + k0 + nt * 8 + 2 * lr);
                s[nt][0] = s[nt][0] * scale2 + ma.x * LOG2E;
                s[nt][1] = s[nt][1] * scale2 + ma.y * LOG2E;
                s[nt][2] = s[nt][2] * scale2 + mb.x * LOG2E;
                s[nt][3] = s[nt][3] * scale2 + mb.y * LOG2E;
            }
        } else {
#pragma unroll
            for (int nt = 0; nt < 8; nt++) {
                s[nt][0] *= scale2;
                s[nt][1] *= scale2;
                s[nt][2] *= scale2;
                s[nt][3] *= scale2;
            }
        }

        float r0 = -1e30f, r1 = -1e30f;
#pragma unroll
        for (int nt = 0; nt < 8; nt++) {
            r0 = fmaxf(r0, fmaxf(s[nt][0], s[nt][1]));
            r1 = fmaxf(r1, fmaxf(s[nt][2], s[nt][3]));
        }
        r0 = fmaxf(r0, __shfl_xor_sync(0xffffffffu, r0, 1));
        r0 = fmaxf(r0, __shfl_xor_sync(0xffffffffu, r0, 2));
        r1 = fmaxf(r1, __shfl_xor_sync(0xffffffffu, r1, 1));
        r1 = fmaxf(r1, __shfl_xor_sync(0xffffffffu, r1, 2));

        float nm0 = fmaxf(m0r, r0), nm1 = fmaxf(m1r, r1);
        float c0 = exp2f(m0r - nm0), c1 = exp2f(m1r - nm1);
        float sum0 = 0.f, sum1 = 0.f;
#pragma unroll
        for (int nt = 0; nt < 8; nt++) {
            s[nt][0] = exp2f(s[nt][0] - nm0);
            s[nt][1] = exp2f(s[nt][1] - nm0);
            s[nt][2] = exp2f(s[nt][2] - nm1);
            s[nt][3] = exp2f(s[nt][3] - nm1);
            sum0 += s[nt][0] + s[nt][1];
            sum1 += s[nt][2] + s[nt][3];
        }
        sum0 += __shfl_xor_sync(0xffffffffu, sum0, 1);
        sum0 += __shfl_xor_sync(0xffffffffu, sum0, 2);
        sum1 += __shfl_xor_sync(0xffffffffu, sum1, 1);
        sum1 += __shfl_xor_sync(0xffffffffu, sum1, 2);
        l0r = l0r * c0 + sum0;
        l1r = l1r * c1 + sum1;
        m0r = nm0; m1r = nm1;
#pragma unroll
        for (int nt = 0; nt < 8; nt++) {
            o[nt][0] *= c0; o[nt][1] *= c0;
            o[nt][2] *= c1; o[nt][3] *= c1;
        }

#pragma unroll
        for (int kc = 0; kc < 4; kc++) {
            u32 ph[4], pl[4];
            split2(s[2 * kc][0], s[2 * kc][1], ph[0], pl[0]);
            split2(s[2 * kc][2], s[2 * kc][3], ph[1], pl[1]);
            split2(s[2 * kc + 1][0], s[2 * kc + 1][1], ph[2], pl[2]);
            split2(s[2 * kc + 1][2], s[2 * kc + 1][3], ph[3], pl[3]);
#pragma unroll
            for (int nt = 0; nt < 8; nt++) {
                int base = (nt * 8 + lq) * 36 + 8 * kc + lr;
                u32 bhf[2] = {Vh[base], Vh[base + 4]};
                u32 blf[2] = {Vl[base], Vl[base + 4]};
                mma16816(o[nt], ph, bhf);
                mma16816(o[nt], ph, blf);
                mma16816(o[nt], pl, bhf);
            }
        }
        __syncthreads();
    }

    float inv0 = 1.f / l0r, inv1 = 1.f / l1r;
    size_t r0c = ((size_t)b * SS + qw + lq) * 512 + h * 32;
    size_t r1c = r0c + 8 * 512;
#pragma unroll
    for (int nt = 0; nt < 8; nt++) {
        int pidx = (nt >> 1) * 8 + 2 * lr + (nt & 1);  // kperm of nt*4+lr
        u32 hh, ll;
        split2(o[nt][0] * inv0, o[nt][1] * inv0, hh, ll);
        d_Ci[r0c + pidx] = make_uint2(hh, ll);
        split2(o[nt][2] * inv1, o[nt][3] * inv1, hh, ll);
        d_Ci[r1c + pidx] = make_uint2(hh, ll);
    }
}

// ---------------------------------------------------------------------------
extern "C" void kernel_launch(void* const* d_in, const int* in_sizes, int n_in,
                              void* d_out, int out_size) {
    const float* x    = (const float*)d_in[0];
    const float* mask = (const float*)d_in[1];
    const float* Wqkv = (const float*)d_in[2];
    const float* bqkv = (const float*)d_in[3];
    const float* Wout = (const float*)d_in[4];
    const float* bout = (const float*)d_in[5];
    float*       out  = (float*)d_out;

    (void)in_sizes; (void)n_in; (void)out_size;

    uint2 *xi, *wqi, *woi, *ci;
    cudaGetSymbolAddress((void**)&xi, d_Xi);
    cudaGetSymbolAddress((void**)&wqi, d_Wqi);
    cudaGetSymbolAddress((void**)&woi, d_Woi);
    cudaGetSymbolAddress((void**)&ci, d_Ci);

    cudaFuncSetAttribute(mm_bf16<0>, cudaFuncAttributeMaxDynamicSharedMemorySize,
                         MM_SMEM);
    cudaFuncSetAttribute(mm_bf16<1>, cudaFuncAttributeMaxDynamicSharedMemorySize,
                         MM_SMEM);
    cudaFuncSetAttribute(attn_mma, cudaFuncAttributeMaxDynamicSharedMemorySize,
                         AT_SMEM);

    // 0) one-time splits + mask zero check
    mask_zero_flag<<<1, 1>>>();
    mask_check<<<512, 256>>>(mask);
    prep_x<<<4096, 256>>>(x);
    prep_wt<3072><<<dim3(3072 / 32, 16), dim3(32, 32)>>>(Wqkv, wqi);
    prep_wt<1024><<<dim3(1024 / 32, 16), dim3(32, 32)>>>(Wout, woi);

    // 1) QKV projection
    mm_bf16<0><<<dim3(3072 / 128, 8192 / 128), 256, MM_SMEM>>>(
        xi, wqi, bqkv, nullptr);

    // 2) attention
    attn_mma<<<dim3(SS / 128, HH, BB), 256, AT_SMEM>>>(mask);

    // 3) output projection
    mm_bf16<1><<<dim3(1024 / 128, 8192 / 128), 256, MM_SMEM>>>(
        ci, woi, bout, out);
}

// round 17
// speedup vs baseline: 1.0295x; 1.0295x over previous
#include <cuda_runtime.h>
#include <cuda_bf16.h>

#define BB 4
#define SS 2048
#define DD 1024
#define HH 16
#define HD 64

typedef unsigned long long u64;
typedef unsigned int u32;
typedef unsigned short u16;

// ---- cp.async ----
#define CP16(dst, src) \
    asm volatile("cp.async.cg.shared.global [%0], [%1], 16;" :: "r"(dst), "l"(src))
#define CPC asm volatile("cp.async.commit_group;")
#define CPW(n) asm volatile("cp.async.wait_group %0;" :: "n"(n))

// ---- bf16 helpers ----
__device__ __forceinline__ u32 pkbf2(float a, float b) {
    __nv_bfloat162 t = __floats2bfloat162_rn(a, b);
    return *reinterpret_cast<u32*>(&t);
}
__device__ __forceinline__ float bf2f(u16 h) {
    __nv_bfloat16 t = *reinterpret_cast<__nv_bfloat16*>(&h);
    return __bfloat162float(t);
}
__device__ __forceinline__ void split2(float a, float b, u32& hi, u32& lo) {
    hi = pkbf2(a, b);
    float ra = a - bf2f((u16)(hi & 0xffff));
    float rb = b - bf2f((u16)(hi >> 16));
    lo = pkbf2(ra, rb);
}
__device__ __forceinline__ u32 smem_u32(const void* p) {
    u32 a;
    asm("{ .reg .u64 t; cvta.to.shared.u64 t, %1; cvt.u32.u64 %0, t; }"
        : "=r"(a) : "l"(p));
    return a;
}

// mma.sync m16n8k16 bf16
__device__ __forceinline__ void mma16816(float* d, const u32* a, const u32* b) {
    asm volatile(
        "mma.sync.aligned.m16n8k16.row.col.f32.bf16.bf16.f32 "
        "{%0,%1,%2,%3}, {%4,%5,%6,%7}, {%8,%9}, {%0,%1,%2,%3};"
        : "+f"(d[0]), "+f"(d[1]), "+f"(d[2]), "+f"(d[3])
        : "r"(a[0]), "r"(a[1]), "r"(a[2]), "r"(a[3]), "r"(b[0]), "r"(b[1]));
}

// kpair permutation within each k16 group: [0,4,1,5,2,6,3,7]
__device__ __forceinline__ int kperm(int g) {
    int j = g & 7;
    return (g & ~7) | (2 * (j & 3) + (j >> 2));
}

// ---- device scratch (R10-proven layouts) ----
__device__ uint2 d_Xi[8192 * 512];
__device__ uint2 d_Wqi[3072 * 512];
__device__ uint2 d_Woi[1024 * 512];
__device__ uint2 d_Qi[(size_t)BB * HH * SS * 32];
__device__ uint2 d_Ki[(size_t)BB * HH * SS * 32];
__device__ u16   d_Vth[(size_t)BB * HH * HD * SS];
__device__ u16   d_Vtl[(size_t)BB * HH * HD * SS];
__device__ uint2 d_Ci[8192 * 512];
__device__ int   d_mask_nz;

// ---------------------------------------------------------------------------
// mask zero-check
// ---------------------------------------------------------------------------
__global__ void mask_zero_flag() {
    if (blockIdx.x == 0 && threadIdx.x == 0) d_mask_nz = 0;
}
__global__ void mask_check(const float* __restrict__ mask) {
    const int N = SS * SS / 4;
    int nz = 0;
    for (int i = blockIdx.x * blockDim.x + threadIdx.x; i < N;
         i += gridDim.x * blockDim.x) {
        float4 v = ((const float4*)mask)[i];
        if (v.x != 0.f || v.y != 0.f || v.z != 0.f || v.w != 0.f) nz = 1;
    }
    if (__syncthreads_or(nz) && threadIdx.x == 0) d_mask_nz = 1;
}

// ---------------------------------------------------------------------------
// prep: fp32 -> interleaved {hi,lo}, kpair-permuted
// ---------------------------------------------------------------------------
__global__ void prep_x(const float* __restrict__ X) {
    const int N = 8192 * 256;  // float4 count
    for (int i = blockIdx.x * blockDim.x + threadIdx.x; i < N;
         i += gridDim.x * blockDim.x) {
        float4 v = ((const float4*)X)[i];
        u32 h0, l0, h1, l1;
        split2(v.x, v.y, h0, l0);
        split2(v.z, v.w, h1, l1);
        int row = i >> 8, g2 = (i & 255) * 2;
        d_Xi[(size_t)row * 512 + kperm(g2)]     = make_uint2(h0, l0);
        d_Xi[(size_t)row * 512 + kperm(g2 + 1)] = make_uint2(h1, l1);
    }
}

template <int NTOT>
__global__ void prep_wt(const float* __restrict__ W, uint2* __restrict__ Wt) {
    __shared__ uint2 s[32][33];
    int tx = threadIdx.x, ty = threadIdx.y;
    int n  = blockIdx.x * 32 + tx;
    int k2 = blockIdx.y * 32 + ty;
    float w0 = W[(size_t)(2 * k2) * NTOT + n];
    float w1 = W[(size_t)(2 * k2 + 1) * NTOT + n];
    u32 h, l;
    split2(w0, w1, h, l);
    s[ty][tx] = make_uint2(h, l);
    __syncthreads();
    int outn = blockIdx.x * 32 + ty;
    int outk = blockIdx.y * 32 + tx;
    Wt[(size_t)outn * 512 + kperm(outk)] = s[tx][ty];
}

// ---------------------------------------------------------------------------
// GEMM: 4-stage cp.async pipeline, k16 chunks — EXACT R10 (proven optimum)
// ---------------------------------------------------------------------------
#define MM_SMEM (4 * 16384)

template <int MODE>
__global__ void __launch_bounds__(256, 2) mm_bf16(const uint2* __restrict__ Ai,
                                                  const uint2* __restrict__ Bi,
                                                  const float* __restrict__ bias,
                                                  float* __restrict__ outp) {
    extern __shared__ uint4 dynsm4[];
    const u32 sb = smem_u32(dynsm4);

    const int tid  = threadIdx.x;
    const int wid  = tid >> 5, lane = tid & 31;
    const int wm   = wid & 1, wn = wid >> 1;
    const int m0   = blockIdx.y * 128;
    const int n0   = blockIdx.x * 128;
    const int lq   = lane >> 2;
    const int lr   = lane & 3;

    const int srow = tid >> 1;
    const int sp   = (tid & 1) * 2;
    const uint2* aS = Ai + (size_t)(m0 + srow) * 512 + sp * 2;
    const uint2* bS = Bi + (size_t)(n0 + srow) * 512 + sp * 2;
    const u32 dAb = sb + srow * 64 + sp * 16;
    const u32 dBb = sb + 8192 + srow * 64 + sp * 16;

    float d[4][4][4];
#pragma unroll
    for (int mt = 0; mt < 4; mt++)
#pragma unroll
        for (int nt = 0; nt < 4; nt++)
#pragma unroll
            for (int e = 0; e < 4; e++) d[mt][nt][e] = 0.f;

    // prologue: stage chunks 0,1,2
#pragma unroll
    for (int c = 0; c < 3; c++) {
        const u32 off = c * 16384;
        CP16(dAb + off, aS + c * 8);
        CP16(dAb + off + 16, aS + c * 8 + 2);
        CP16(dBb + off, bS + c * 8);
        CP16(dBb + off + 16, bS + c * 8 + 2);
        CPC;
    }

    for (int c = 0; c < 64; c++) {
        CPW(2);
        __syncthreads();

        const uint4* A4 = dynsm4 + (c & 3) * 1024;
        const uint4* B4 = A4 + 512;

        u32 bh[4][2], bl[4][2];
#pragma unroll
        for (int nt = 0; nt < 4; nt++) {
            uint4 v = B4[(wn * 32 + nt * 8 + lq) * 4 + lr];
            bh[nt][0] = v.x; bh[nt][1] = v.z;
            bl[nt][0] = v.y; bl[nt][1] = v.w;
        }
#pragma unroll
        for (int mt = 0; mt < 4; mt++) {
            int row  = wm * 64 + mt * 16 + lq;
            uint4 v0 = A4[row * 4 + lr];
            uint4 v1 = A4[(row + 8) * 4 + lr];
            u32 ah[4] = {v0.x, v1.x, v0.z, v1.z};
            u32 al[4] = {v0.y, v1.y, v0.w, v1.w};
#pragma unroll
            for (int nt = 0; nt < 4; nt++) {
                mma16816(d[mt][nt], ah, bh[nt]);
                mma16816(d[mt][nt], ah, bl[nt]);
                mma16816(d[mt][nt], al, bh[nt]);
            }
        }

        // stage chunk c+3 into buf (c+3)&3 (readers finished at this sync)
        if (c + 3 < 64) {
            const u32 off = ((c + 3) & 3) * 16384;
            CP16(dAb + off, aS + (c + 3) * 8);
            CP16(dAb + off + 16, aS + (c + 3) * 8 + 2);
            CP16(dBb + off, bS + (c + 3) * 8);
            CP16(dBb + off + 16, bS + (c + 3) * 8 + 2);
        }
        CPC;  // empty group at tail keeps wait-count uniform
    }

    // --- epilogue (R10) ---
#pragma unroll
    for (int mt = 0; mt < 4; mt++) {
#pragma unroll
        for (int nt = 0; nt < 4; nt++) {
            int m = m0 + wm * 64 + mt * 16 + lq;
            int n = n0 + wn * 32 + nt * 8 + lr * 2;
            float2 bv = *(const float2*)&bias[n];
            float o00 = d[mt][nt][0] + bv.x, o01 = d[mt][nt][1] + bv.y;
            float o10 = d[mt][nt][2] + bv.x, o11 = d[mt][nt][3] + bv.y;
            if (MODE == 1) {
                *(float2*)&outp[(size_t)m * 1024 + n]       = make_float2(o00, o01);
                *(float2*)&outp[(size_t)(m + 8) * 1024 + n] = make_float2(o10, o11);
            } else {
                int bb = m >> 11, ssq = m & 2047;
                int which = n >> 10;
                int head  = (n & 1023) >> 6;
                int hd    = n & 63;
                u32 h0, l0, h1, l1;
                split2(o00, o01, h0, l0);
                split2(o10, o11, h1, l1);
                if (which < 2) {
                    uint2* dst = (which == 0) ? d_Qi : d_Ki;
                    size_t idx =
                        (((size_t)bb * HH + head) * SS + ssq) * 32 + (hd >> 1);
                    dst[idx]       = make_uint2(h0, l0);
                    dst[idx + 256] = make_uint2(h1, l1);
                } else {
                    size_t base = (((size_t)bb * HH + head) * HD + hd) * SS;
                    d_Vth[base + ssq]          = (u16)(h0 & 0xffff);
                    d_Vth[base + SS + ssq]     = (u16)(h0 >> 16);
                    d_Vtl[base + ssq]          = (u16)(l0 & 0xffff);
                    d_Vtl[base + SS + ssq]     = (u16)(l0 >> 16);
                    d_Vth[base + ssq + 8]      = (u16)(h1 & 0xffff);
                    d_Vth[base + SS + ssq + 8] = (u16)(h1 >> 16);
                    d_Vtl[base + ssq + 8]      = (u16)(l1 & 0xffff);
                    d_Vtl[base + SS + ssq + 8] = (u16)(l1 >> 16);
                }
            }
        }
    }
}

// ---------------------------------------------------------------------------
// Flash attention — R15 winner + conditional O-rescale (skip when max stable).
// ---------------------------------------------------------------------------
#define AT_SMEM (2 * 36864)

__global__ void __launch_bounds__(256, 2) attn_mma(const float* __restrict__ mask) {
    extern __shared__ char atsm[];
    const u32 sb = smem_u32(atsm);

    const int tid  = threadIdx.x;
    const int wid  = tid >> 5, lane = tid & 31;
    const int lq   = lane >> 2, lr = lane & 3;
    const int qt = blockIdx.x, h = blockIdx.y, b = blockIdx.z;
    const size_t bh = (size_t)b * HH + h;
    const int q0 = qt * 128;
    const int qw = q0 + wid * 16;
    const int mnz = d_mask_nz;   // uniform

    u32 qfh[4][4], qfl[4][4];
    {
        const uint2* qp  = d_Qi + (bh * SS + qw + lq) * 32;
        const uint2* qp1 = qp + 256;
#pragma unroll
        for (int kc = 0; kc < 4; kc++) {
            uint2 a0 = qp[8 * kc + lr];
            uint2 a1 = qp1[8 * kc + lr];
            uint2 a2 = qp[8 * kc + 4 + lr];
            uint2 a3 = qp1[8 * kc + 4 + lr];
            qfh[kc][0] = a0.x; qfh[kc][1] = a1.x; qfh[kc][2] = a2.x; qfh[kc][3] = a3.x;
            qfl[kc][0] = a0.y; qfl[kc][1] = a1.y; qfl[kc][2] = a2.y; qfl[kc][3] = a3.y;
        }
    }

    float o[8][4];
#pragma unroll
    for (int nt = 0; nt < 8; nt++)
#pragma unroll
        for (int e = 0; e < 4; e++) o[nt][e] = 0.f;
    float m0r = -1e30f, m1r = -1e30f, l0r = 0.f, l1r = 0.f;

    const float LOG2E  = 1.44269504f;
    const float scale2 = 0.125f * LOG2E;
    const float* mp0 = mask + (size_t)(qw + lq) * SS;
    const float* mp1 = mask + (size_t)(qw + lq + 8) * SS;

    const int krow = tid >> 2, ku = (tid & 3) * 4;
    const int vrow = tid >> 2, vu = (tid & 3) * 2;
    const uint2* kSrc = d_Ki + (bh * SS + krow) * 32 + ku * 2;
    const char* vhSrc = (const char*)d_Vth + ((bh * HD + vrow) * SS) * 2 + vu * 16;
    const char* vlSrc = (const char*)d_Vtl + ((bh * HD + vrow) * SS) * 2 + vu * 16;
    const u32 dK  = sb + krow * 288 + ku * 16;
    const u32 dVh = sb + 18432 + vrow * 144 + vu * 16;
    const u32 dVl = sb + 27648 + vrow * 144 + vu * 16;

#pragma unroll
    for (int q = 0; q < 4; q++) CP16(dK + q * 16, kSrc + q * 2);
#pragma unroll
    for (int q = 0; q < 2; q++) {
        CP16(dVh + q * 16, vhSrc + q * 16);
        CP16(dVl + q * 16, vlSrc + q * 16);
    }
    CPC;

    for (int kt = 0; kt < SS / 64; kt++) {
        const int k0  = kt * 64;
        const int buf = kt & 1;
        if (kt < 31) {
            const u32 off = ((kt + 1) & 1) * 36864;
            const uint2* kN = kSrc + (size_t)(kt + 1) * 64 * 32;
            const char* vhN = vhSrc + (kt + 1) * 128;
            const char* vlN = vlSrc + (kt + 1) * 128;
#pragma unroll
            for (int q = 0; q < 4; q++) CP16(dK + off + q * 16, kN + q * 2);
#pragma unroll
            for (int q = 0; q < 2; q++) {
                CP16(dVh + off + q * 16, vhN + q * 16);
                CP16(dVl + off + q * 16, vlN + q * 16);
            }
            CPC;
            CPW(1);
        } else {
            CPW(0);
        }
        __syncthreads();

        const uint2* K2 = (const uint2*)(atsm + buf * 36864);
        const u32* Vh   = (const u32*)(atsm + buf * 36864 + 18432);
        const u32* Vl   = (const u32*)(atsm + buf * 36864 + 27648);

        float s[8][4];
#pragma unroll
        for (int nt = 0; nt < 8; nt++)
#pragma unroll
            for (int e = 0; e < 4; e++) s[nt][e] = 0.f;

#pragma unroll
        for (int kc = 0; kc < 4; kc++) {
#pragma unroll
            for (int nt = 0; nt < 8; nt++) {
                int base = (nt * 8 + lq) * 36 + 8 * kc + lr;
                uint2 r0 = K2[base];
                uint2 r1 = K2[base + 4];
                u32 bhf[2] = {r0.x, r1.x};
                u32 blf[2] = {r0.y, r1.y};
                mma16816(s[nt], qfh[kc], bhf);
                mma16816(s[nt], qfh[kc], blf);
                mma16816(s[nt], qfl[kc], bhf);
            }
        }

        if (mnz) {
#pragma unroll
            for (int nt = 0; nt < 8; nt++) {
                float2 ma = *(const float2*)(mp0 + k0 + nt * 8 + 2 * lr);
                float2 mb = *(const float2*)(mp1 + k0 + nt * 8 + 2 * lr);
                s[nt][0] = s[nt][0] * scale2 + ma.x * LOG2E;
                s[nt][1] = s[nt][1] * scale2 + ma.y * LOG2E;
                s[nt][2] = s[nt][2] * scale2 + mb.x * LOG2E;
                s[nt][3] = s[nt][3] * scale2 + mb.y * LOG2E;
            }
        } else {
#pragma unroll
            for (int nt = 0; nt < 8; nt++) {
                s[nt][0] *= scale2;
                s[nt][1] *= scale2;
                s[nt][2] *= scale2;
                s[nt][3] *= scale2;
            }
        }

        float r0 = -1e30f, r1 = -1e30f;
#pragma unroll
        for (int nt = 0; nt < 8; nt++) {
            r0 = fmaxf(r0, fmaxf(s[nt][0], s[nt][1]));
            r1 = fmaxf(r1, fmaxf(s[nt][2], s[nt][3]));
        }
        r0 = fmaxf(r0, __shfl_xor_sync(0xffffffffu, r0, 1));
        r0 = fmaxf(r0, __shfl_xor_sync(0xffffffffu, r0, 2));
        r1 = fmaxf(r1, __shfl_xor_sync(0xffffffffu, r1, 1));
        r1 = fmaxf(r1, __shfl_xor_sync(0xffffffffu, r1, 2));

        float nm0 = fmaxf(m0r, r0), nm1 = fmaxf(m1r, r1);
        // conditional rescale: skip exp2+32 mults when max unchanged (common)
        if (nm0 != m0r || nm1 != m1r) {
            float c0 = exp2f(m0r - nm0), c1 = exp2f(m1r - nm1);
            l0r *= c0;
            l1r *= c1;
#pragma unroll
            for (int nt = 0; nt < 8; nt++) {
                o[nt][0] *= c0; o[nt][1] *= c0;
                o[nt][2] *= c1; o[nt][3] *= c1;
            }
            m0r = nm0; m1r = nm1;
        }
        float sum0 = 0.f, sum1 = 0.f;
#pragma unroll
        for (int nt = 0; nt < 8; nt++) {
            s[nt][0] = exp2f(s[nt][0] - m0r);
            s[nt][1] = exp2f(s[nt][1] - m0r);
            s[nt][2] = exp2f(s[nt][2] - m1r);
            s[nt][3] = exp2f(s[nt][3] - m1r);
            sum0 += s[nt][0] + s[nt][1];
            sum1 += s[nt][2] + s[nt][3];
        }
        sum0 += __shfl_xor_sync(0xffffffffu, sum0, 1);
        sum0 += __shfl_xor_sync(0xffffffffu, sum0, 2);
        sum1 += __shfl_xor_sync(0xffffffffu, sum1, 1);
        sum1 += __shfl_xor_sync(0xffffffffu, sum1, 2);
        l0r += sum0;
        l1r += sum1;

#pragma unroll
        for (int kc = 0; kc < 4; kc++) {
            u32 ph[4], pl[4];
            split2(s[2 * kc][0], s[2 * kc][1], ph[0], pl[0]);
            split2(s[2 * kc][2], s[2 * kc][3], ph[1], pl[1]);
            split2(s[2 * kc + 1][0], s[2 * kc + 1][1], ph[2], pl[2]);
            split2(s[2 * kc + 1][2], s[2 * kc + 1][3], ph[3], pl[3]);
#pragma unroll
            for (int nt = 0; nt < 8; nt++) {
                int base = (nt * 8 + lq) * 36 + 8 * kc + lr;
                u32 bhf[2] = {Vh[base], Vh[base + 4]};
                u32 blf[2] = {Vl[base], Vl[base + 4]};
                mma16816(o[nt], ph, bhf);
                mma16816(o[nt], ph, blf);
                mma16816(o[nt], pl, bhf);
            }
        }
        __syncthreads();
    }

    float inv0 = 1.f / l0r, inv1 = 1.f / l1r;
    size_t r0c = ((size_t)b * SS + qw + lq) * 512 + h * 32;
    size_t r1c = r0c + 8 * 512;
#pragma unroll
    for (int nt = 0; nt < 8; nt++) {
        int pidx = (nt >> 1) * 8 + 2 * lr + (nt & 1);  // kperm of nt*4+lr
        u32 hh, ll;
        split2(o[nt][0] * inv0, o[nt][1] * inv0, hh, ll);
        d_Ci[r0c + pidx] = make_uint2(hh, ll);
        split2(o[nt][2] * inv1, o[nt][3] * inv1, hh, ll);
        d_Ci[r1c + pidx] = make_uint2(hh, ll);
    }
}

// ---------------------------------------------------------------------------
extern "C" void kernel_launch(void* const* d_in, const int* in_sizes, int n_in,
                              void* d_out, int out_size) {
    const float* x    = (const float*)d_in[0];
    const float* mask = (const float*)d_in[1];
    const float* Wqkv = (const float*)d_in[2];
    const float* bqkv = (const float*)d_in[3];
    const float* Wout = (const float*)d_in[4];
    const float* bout = (const float*)d_in[5];
    float*       out  = (float*)d_out;

    (void)in_sizes; (void)n_in; (void)out_size;

    uint2 *xi, *wqi, *woi, *ci;
    cudaGetSymbolAddress((void**)&xi, d_Xi);
    cudaGetSymbolAddress((void**)&wqi, d_Wqi);
    cudaGetSymbolAddress((void**)&woi, d_Woi);
    cudaGetSymbolAddress((void**)&ci, d_Ci);

    cudaFuncSetAttribute(mm_bf16<0>, cudaFuncAttributeMaxDynamicSharedMemorySize,
                         MM_SMEM);
    cudaFuncSetAttribute(mm_bf16<1>, cudaFuncAttributeMaxDynamicSharedMemorySize,
                         MM_SMEM);
    cudaFuncSetAttribute(attn_mma, cudaFuncAttributeMaxDynamicSharedMemorySize,
                         AT_SMEM);

    // 0) one-time splits + mask zero check
    mask_zero_flag<<<1, 1>>>();
    mask_check<<<512, 256>>>(mask);
    prep_x<<<4096, 256>>>(x);
    prep_wt<3072><<<dim3(3072 / 32, 16), dim3(32, 32)>>>(Wqkv, wqi);
    prep_wt<1024><<<dim3(1024 / 32, 16), dim3(32, 32)>>>(Wout, woi);

    // 1) QKV projection
    mm_bf16<0><<<dim3(3072 / 128, 8192 / 128), 256, MM_SMEM>>>(
        xi, wqi, bqkv, nullptr);

    // 2) attention
    attn_mma<<<dim3(SS / 128, HH, BB), 256, AT_SMEM>>>(mask);

    // 3) output projection
    mm_bf16<1><<<dim3(1024 / 128, 8192 / 128), 256, MM_SMEM>>>(
        ci, woi, bout, out);
}